// round 12
// baseline (speedup 1.0000x reference)
#include <cuda_runtime.h>
#include <math_constants.h>

#define Bb 4
#define Pp 8192
#define Cc 64
#define Mm 2048
#define NB 64
#define OUTC 384
#define HT_STRIDE 68

// per-wg smem floats: union(hT 67*68 + h1T 128*68 = 13260; sd needs 8192) -> 13264 pad
// + sd2 64 + snn 64 + swv/swi 32  -> 13424 -> pad 13440
#define WGF 13440

__device__ unsigned g_progress[Bb];

// ---------------- packed f32x2 helpers (bitwise == two scalar rn ops) -------
typedef unsigned long long u64;

__device__ __forceinline__ u64 pk2(float lo, float hi) {
    u64 r; asm("mov.b64 %0, {%1, %2};" : "=l"(r) : "f"(lo), "f"(hi)); return r;
}
__device__ __forceinline__ void upk2(float& lo, float& hi, u64 v) {
    asm("mov.b64 {%0, %1}, %2;" : "=f"(lo), "=f"(hi) : "l"(v));
}
__device__ __forceinline__ u64 add2(u64 a, u64 b) {
    u64 d; asm("add.rn.f32x2 %0, %1, %2;" : "=l"(d) : "l"(a), "l"(b)); return d;
}
__device__ __forceinline__ u64 mul2(u64 a, u64 b) {
    u64 d; asm("mul.rn.f32x2 %0, %1, %2;" : "=l"(d) : "l"(a), "l"(b)); return d;
}
__device__ __forceinline__ u64 fma2(u64 a, u64 b, u64 c) {
    u64 d; asm("fma.rn.f32x2 %0, %1, %2, %3;" : "=l"(d) : "l"(a), "l"(b), "l"(c)); return d;
}
__device__ __forceinline__ unsigned ld_acq(const unsigned* p) {
    unsigned v; asm volatile("ld.acquire.gpu.global.u32 %0, [%1];" : "=r"(v) : "l"(p)); return v;
}
__device__ __forceinline__ void st_rel(unsigned* p, unsigned v) {
    asm volatile("st.release.gpu.global.u32 [%0], %1;" :: "l"(p), "r"(v) : "memory");
}
__device__ __forceinline__ void wgbar(int id) {
    asm volatile("bar.sync %0, 256;" :: "r"(id) : "memory");
}

// ---------------------------------------------------------------------------
// FPS for one batch, 512 threads (16 points/thread). Bitwise-identical
// selection to the JAX scan. Publishes progress[b] = t+1 after writing ps[t].
// ---------------------------------------------------------------------------
__device__ void fps_block(int b, const float* __restrict__ pos,
                          float* __restrict__ pos_s, unsigned* __restrict__ smu)
{
    const float* pb = pos + (size_t)b * Pp * 3;
    float* ps = pos_s + (size_t)b * Mm * 3;
    const int tid = threadIdx.x;
    const int lane = tid & 31, wrp = tid >> 5;     // 16 warps

    u64 px2[8], py2[8], pz2[8];
    unsigned mind[16];
#pragma unroll
    for (int q = 0; q < 8; q++) {
        int p0 = tid + (2 * q) * 512;
        int p1 = p0 + 512;
        px2[q] = pk2(pb[3 * p0],     pb[3 * p1]);
        py2[q] = pk2(pb[3 * p0 + 1], pb[3 * p1 + 1]);
        pz2[q] = pk2(pb[3 * p0 + 2], pb[3 * p1 + 2]);
    }
#pragma unroll
    for (int i = 0; i < 16; i++) mind[i] = __float_as_uint(1e30f);

    unsigned* swv = smu;         // [2][16]
    unsigned* swi = smu + 32;    // [2][16]

    unsigned sel = 0;
    for (int t = 0; t < Mm; t++) {
        float lx = pb[3 * sel], ly = pb[3 * sel + 1], lz = pb[3 * sel + 2];
        if (tid == 0) {
            ps[3 * t] = lx; ps[3 * t + 1] = ly; ps[3 * t + 2] = lz;
            st_rel(&g_progress[b], (unsigned)(t + 1));
        }

        u64 nx2 = pk2(-lx, -lx);
        u64 ny2 = pk2(-ly, -ly);
        u64 nz2 = pk2(-lz, -lz);

#pragma unroll
        for (int q = 0; q < 8; q++) {
            u64 dx = add2(px2[q], nx2);
            u64 dy = add2(py2[q], ny2);
            u64 dz = add2(pz2[q], nz2);
            u64 s  = add2(add2(mul2(dx, dx), mul2(dy, dy)), mul2(dz, dz));
            float dlo, dhi;
            upk2(dlo, dhi, s);
            mind[2 * q]     = min(mind[2 * q],     __float_as_uint(dlo));
            mind[2 * q + 1] = min(mind[2 * q + 1], __float_as_uint(dhi));
        }
        // 15-op max tree (d2 >= 0 -> uint order == float order)
        unsigned bv;
        {
            unsigned a0 = max(mind[0], mind[1]),  a1 = max(mind[2], mind[3]);
            unsigned a2 = max(mind[4], mind[5]),  a3 = max(mind[6], mind[7]);
            unsigned a4 = max(mind[8], mind[9]),  a5 = max(mind[10], mind[11]);
            unsigned a6 = max(mind[12], mind[13]), a7 = max(mind[14], mind[15]);
            unsigned b0 = max(a0, a1), b1 = max(a2, a3), b2 = max(a4, a5), b3 = max(a6, a7);
            bv = max(max(b0, b1), max(b2, b3));
        }

        unsigned wv = __reduce_max_sync(0xffffffffu, bv);
        unsigned cand = 0xffffffffu;
        if (bv == wv) {
#pragma unroll
            for (int i = 15; i >= 0; i--)
                if (mind[i] == wv) cand = (unsigned)(tid + (i << 9));
        }
        unsigned wi = __reduce_min_sync(0xffffffffu, cand);

        const int buf = (t & 1) * 16;
        if (lane == 0) { swv[buf + wrp] = wv; swi[buf + wrp] = wi; }
        __syncthreads();

        unsigned v  = (lane < 16) ? swv[buf + lane] : 0u;
        unsigned ii = (lane < 16) ? swi[buf + lane] : 0xffffffffu;
        unsigned gv = __reduce_max_sync(0xffffffffu, v);
        unsigned c2 = (v == gv && lane < 16) ? ii : 0xffffffffu;
        sel = __reduce_min_sync(0xffffffffu, c2);
    }
}

// ---------------------------------------------------------------------------
// per-centroid MLP branch (256-thread sub-unit, named barrier `barid`).
// Warp tile = 32k x (H/W)j ; lane = (kk 4) x (lj 8); thread = 8k x JU j.
// Weight LDGs span <=256B per warp (1-2 wf); activation LDS spans 128B (1 wf).
// Double-buffered weight prefetch. Accumulation order over c/i identical to
// reference (bitwise).
// ---------------------------------------------------------------------------
template<int K, int H1, int H2>
__device__ __forceinline__ void run_branch(
    const float* __restrict__ hT, float* __restrict__ h1T,
    const float* __restrict__ sd2,
    const float* __restrict__ W1, const float* __restrict__ B1b,
    const float* __restrict__ W2, const float* __restrict__ B2b,
    float* __restrict__ outrow, float r2, int t, int barid)
{
    constexpr int WK = K / 32;              // k warp-groups (b2:2, b1:1)
    constexpr int WI = 8 / WK, SI = H1 / WI, IU = SI / 8;   // GEMM1: thread i count
    constexpr int WJ = 8 / WK, SJ = H2 / WJ, JU = SJ / 8;   // GEMM2: thread j count
    constexpr int ROWS = 4 * WK;            // reduction rows

    const int w = t >> 5, lane = t & 31;
    const int kk = lane >> 3, lj = lane & 7;     // kk 0..3, lj 0..7
    const int wk = w % WK;
    const int wg = w / WK;
    const int kbase = wk * 32 + kk * 8;          // 8 consecutive k per thread

    // ---- GEMM1: h1[i][k] = relu(sum_c hT[c][k]*W1[c][i] + b1[i]) ----
    {
        const int i0 = wg * SI + lj * IU;

        auto lda = [&](float* a, int c) {
            const float4* hp = (const float4*)(hT + c * HT_STRIDE + kbase);
            float4 t0 = hp[0], t1 = hp[1];
            a[0] = t0.x; a[1] = t0.y; a[2] = t0.z; a[3] = t0.w;
            a[4] = t1.x; a[5] = t1.y; a[6] = t1.z; a[7] = t1.w;
        };

        if constexpr (IU == 4) {
            u64 acc[8][2];
#pragma unroll
            for (int v = 0; v < 8; v++) { acc[v][0] = 0ull; acc[v][1] = 0ull; }

            auto ldw = [&](u64* bb, int c) {
                float4 w4 = *(const float4*)(W1 + c * H1 + i0);
                bb[0] = pk2(w4.x, w4.y); bb[1] = pk2(w4.z, w4.w);
            };
            auto body = [&](const float* a, const u64* bb) {
#pragma unroll
                for (int v = 0; v < 8; v++) {
                    u64 av = pk2(a[v], a[v]);
                    acc[v][0] = fma2(av, bb[0], acc[v][0]);
                    acc[v][1] = fma2(av, bb[1], acc[v][1]);
                }
            };

            u64 wbA[2];
            ldw(wbA, 0);
            for (int c = 0; c < 66; c += 2) {
                u64 wbB[2];
                ldw(wbB, c + 1);
                float a0[8]; lda(a0, c);
                body(a0, wbA);
                ldw(wbA, c + 2);          // c+2 <= 66 valid (W1 has 67 rows)
                float a1[8]; lda(a1, c + 1);
                body(a1, wbB);
            }
            { float at[8]; lda(at, 66); body(at, wbA); }   // tail c = 66

            float bias[4];
#pragma unroll
            for (int u = 0; u < 4; u++) bias[u] = B1b[i0 + u];
#pragma unroll
            for (int u = 0; u < 4; u++) {
                float r[8];
#pragma unroll
                for (int v = 0; v < 8; v++) {
                    float lo, hi;
                    upk2(lo, hi, acc[v][u >> 1]);
                    float val = (u & 1) ? hi : lo;
                    r[v] = fmaxf(val + bias[u], 0.f);
                }
                float4 v0 = {r[0], r[1], r[2], r[3]};
                float4 v1 = {r[4], r[5], r[6], r[7]};
                *(float4*)(h1T + (i0 + u) * HT_STRIDE + kbase)     = v0;
                *(float4*)(h1T + (i0 + u) * HT_STRIDE + kbase + 4) = v1;
            }
        } else {   // IU == 1 (branch 1 GEMM1)
            float acc[8];
#pragma unroll
            for (int v = 0; v < 8; v++) acc[v] = 0.f;

            float wA = W1[i0];
            for (int c = 0; c < 66; c += 2) {
                float wB = W1[(c + 1) * H1 + i0];
                float a0[8]; lda(a0, c);
#pragma unroll
                for (int v = 0; v < 8; v++) acc[v] = fmaf(a0[v], wA, acc[v]);
                wA = W1[(c + 2) * H1 + i0];
                float a1[8]; lda(a1, c + 1);
#pragma unroll
                for (int v = 0; v < 8; v++) acc[v] = fmaf(a1[v], wB, acc[v]);
            }
            {
                float at[8]; lda(at, 66);
#pragma unroll
                for (int v = 0; v < 8; v++) acc[v] = fmaf(at[v], wA, acc[v]);
            }
            float bias = B1b[i0];
            float r[8];
#pragma unroll
            for (int v = 0; v < 8; v++) r[v] = fmaxf(acc[v] + bias, 0.f);
            float4 v0 = {r[0], r[1], r[2], r[3]};
            float4 v1 = {r[4], r[5], r[6], r[7]};
            *(float4*)(h1T + i0 * HT_STRIDE + kbase)     = v0;
            *(float4*)(h1T + i0 * HT_STRIDE + kbase + 4) = v1;
        }
    }
    wgbar(barid);

    // ---- GEMM2 + masked max over k ----
    {
        const int j0 = wg * SJ + lj * JU;
        constexpr int JU2 = JU / 2;

        u64 acc[8][JU2];
#pragma unroll
        for (int v = 0; v < 8; v++)
#pragma unroll
            for (int p = 0; p < JU2; p++) acc[v][p] = 0ull;

        auto lda2 = [&](float* a, int i) {
            const float4* hp = (const float4*)(h1T + i * HT_STRIDE + kbase);
            float4 t0 = hp[0], t1 = hp[1];
            a[0] = t0.x; a[1] = t0.y; a[2] = t0.z; a[3] = t0.w;
            a[4] = t1.x; a[5] = t1.y; a[6] = t1.z; a[7] = t1.w;
        };
        auto ldw2 = [&](u64* bb, int i) {
            const float* wp = W2 + i * H2 + j0;
            if constexpr (JU == 8) {
                float4 w0 = *(const float4*)wp;
                float4 w1 = *(const float4*)(wp + 4);
                bb[0] = pk2(w0.x, w0.y); bb[1] = pk2(w0.z, w0.w);
                bb[2] = pk2(w1.x, w1.y); bb[3] = pk2(w1.z, w1.w);
            } else {   // JU == 2
                float2 w0 = *(const float2*)wp;
                bb[0] = pk2(w0.x, w0.y);
            }
        };
        auto body2 = [&](const float* a, const u64* bb) {
#pragma unroll
            for (int v = 0; v < 8; v++) {
                u64 av = pk2(a[v], a[v]);
#pragma unroll
                for (int p = 0; p < JU2; p++)
                    acc[v][p] = fma2(av, bb[p], acc[v][p]);
            }
        };

        u64 wbA[JU2];
        ldw2(wbA, 0);
        for (int i = 0; i < H1; i += 2) {
            u64 wbB[JU2];
            ldw2(wbB, i + 1);
            float a0[8]; lda2(a0, i);
            body2(a0, wbA);
            if (i + 2 < H1) ldw2(wbA, i + 2);
            float a1[8]; lda2(a1, i + 1);
            body2(a1, wbB);
        }

        // per-thread epilogue: bias + relu + mask, max over this thread's 8 k
        float4 s0 = *(const float4*)(sd2 + kbase);
        float4 s1 = *(const float4*)(sd2 + kbase + 4);
        float sdk[8] = {s0.x, s0.y, s0.z, s0.w, s1.x, s1.y, s1.z, s1.w};
        float mx[JU];
#pragma unroll
        for (int p = 0; p < JU2; p++) {
            float blo = B2b[j0 + 2 * p], bhi = B2b[j0 + 2 * p + 1];
            float mlo = -1e30f, mhi = -1e30f;
#pragma unroll
            for (int v = 0; v < 8; v++) {
                float lo, hi;
                upk2(lo, hi, acc[v][p]);
                float vlo = fmaxf(lo + blo, 0.f);
                float vhi = fmaxf(hi + bhi, 0.f);
                if (!(sdk[v] <= r2)) { vlo = -1e30f; vhi = -1e30f; }
                mlo = fmaxf(mlo, vlo);
                mhi = fmaxf(mhi, vhi);
            }
            mx[2 * p] = mlo; mx[2 * p + 1] = mhi;
        }

        wgbar(barid);                 // all h1T reads complete
        float* red = h1T;             // ROWS * H2 <= 2048 floats, fits h1T region
        {
            int row = wk * 4 + kk;
            float* rp = red + row * H2 + j0;
            if constexpr (JU == 8) {
                float4 sv0 = {mx[0], mx[1], mx[2], mx[3]};
                float4 sv1 = {mx[4], mx[5], mx[6], mx[7]};
                *(float4*)rp = sv0;
                *(float4*)(rp + 4) = sv1;
            } else {
                float2 sv = {mx[0], mx[1]};
                *(float2*)rp = sv;
            }
        }
        wgbar(barid);
        for (int j = t; j < H2; j += 256) {
            float mm = red[j];
#pragma unroll
            for (int r = 1; r < ROWS; r++) mm = fmaxf(mm, red[r * H2 + j]);
            outrow[j] = mm;
        }
        wgbar(barid);
    }
}

// ---------------------------------------------------------------------------
// Fused kernel: blocks 0..3 = FPS; blocks 4.. = workers (2 sub-units x 256thr,
// each doing KNN + MLP for one centroid, spin-waiting on FPS progress).
// ---------------------------------------------------------------------------
__global__ void __launch_bounds__(512, 1) fused_kernel(
    const float* __restrict__ x, const float* __restrict__ pos,
    const float* __restrict__ w1_0, const float* __restrict__ b1_0,
    const float* __restrict__ w1_1, const float* __restrict__ b1_1,
    const float* __restrict__ w2_0, const float* __restrict__ b2_0,
    const float* __restrict__ w2_1, const float* __restrict__ b2_1,
    float* __restrict__ out, float* __restrict__ pos_s)
{
    extern __shared__ float sm[];

    if (blockIdx.x < Bb) {
        fps_block(blockIdx.x, pos, pos_s, (unsigned*)sm);
        return;
    }

    const int w  = blockIdx.x - Bb;
    const int wg = threadIdx.x >> 8;          // 0..1
    const int t  = threadIdx.x & 255;
    const int barid = wg + 1;
    const int b  = 2 * (w & 1) + wg;
    const int m  = w >> 1;
    const int bm = b * Mm + m;
    const int lane = t & 31, w8 = t >> 5;

    float*    base = sm + wg * WGF;
    float*    un   = base;                    // union: sd[8192] / hT+h1T[13260]
    float*    sd2s = base + 13264;            // 64
    int*      snn  = (int*)(base + 13328);    // 64
    unsigned* swv  = (unsigned*)(base + 13392);  // [2][8]
    unsigned* swi  = swv + 16;                   // [2][8]

    // ---- wait for our centroid ----
    if (t == 0) {
        while (ld_acq(&g_progress[b]) <= (unsigned)m) __nanosleep(128);
    }
    wgbar(barid);

    const float cx = pos_s[bm * 3], cy = pos_s[bm * 3 + 1], cz = pos_s[bm * 3 + 2];
    const float* pb = pos + (size_t)b * Pp * 3;

    // ---- KNN: distances (packed, bitwise == scalar rn) ----
    float* sd = un;
    unsigned lv = 0x7f800000u, li = 0xffffffffu;
    {
        u64 c2x = pk2(cx, cx), c2y = pk2(cy, cy), c2z = pk2(cz, cz);
        const u64 SMASK = 0x8000000080000000ull;
#pragma unroll 4
        for (int q = 0; q < 16; q++) {
            int p0 = t + (2 * q) * 256;
            int p1 = p0 + 256;
            u64 X = pk2(pb[3 * p0],     pb[3 * p1]);
            u64 Y = pk2(pb[3 * p0 + 1], pb[3 * p1 + 1]);
            u64 Z = pk2(pb[3 * p0 + 2], pb[3 * p1 + 2]);
            u64 dx = add2(c2x, X ^ SMASK);    // cx + (-px) == cx - px (rn exact)
            u64 dy = add2(c2y, Y ^ SMASK);
            u64 dz = add2(c2z, Z ^ SMASK);
            u64 s  = add2(add2(mul2(dx, dx), mul2(dy, dy)), mul2(dz, dz));
            float dlo, dhi;
            upk2(dlo, dhi, s);
            sd[p0] = dlo; sd[p1] = dhi;
            unsigned v0 = __float_as_uint(dlo), v1 = __float_as_uint(dhi);
            if (v0 < lv) { lv = v0; li = (unsigned)p0; }
            if (v1 < lv) { lv = v1; li = (unsigned)p1; }
        }
    }
    wgbar(barid);

    // ---- KNN: 64 rounds of block argmin (value, then lowest index) ----
    for (int r = 0; r < NB; r++) {
        unsigned wv = __reduce_min_sync(0xffffffffu, lv);
        unsigned cand = (lv == wv) ? li : 0xffffffffu;
        unsigned wi = __reduce_min_sync(0xffffffffu, cand);
        const int buf = (r & 1) * 8;
        if (lane == 0) { swv[buf + w8] = wv; swi[buf + w8] = wi; }
        wgbar(barid);
        unsigned v  = (lane < 8) ? swv[buf + lane] : 0xffffffffu;
        unsigned ii = (lane < 8) ? swi[buf + lane] : 0xffffffffu;
        unsigned gv = __reduce_min_sync(0xffffffffu, v);
        unsigned c2 = (v == gv && lane < 8) ? ii : 0xffffffffu;
        unsigned gi = __reduce_min_sync(0xffffffffu, c2);
        if (t == 0) { snn[r] = (int)gi; sd2s[r] = __uint_as_float(gv); }
        unsigned ot = gi & 255u;                 // owner thread in wg
        if ((unsigned)w8 == (ot >> 5)) {         // owner warp: cooperative rescan
            if ((unsigned)t == ot) sd[gi] = CUDART_INF_F;
            __syncwarp();
            unsigned pp = ot + (unsigned)lane * 256u;
            unsigned vv = __float_as_uint(sd[pp]);
            unsigned mv = __reduce_min_sync(0xffffffffu, vv);
            unsigned mc = (vv == mv) ? pp : 0xffffffffu;
            unsigned mi = __reduce_min_sync(0xffffffffu, mc);
            if ((unsigned)t == ot) { lv = mv; li = mi; }
        }
    }
    wgbar(barid);

    // ---- gather hT (overwrites sd region; all KNN reads done) ----
    float* hT  = un;
    float* h1T = un + 67 * HT_STRIDE;
    for (int t2 = t; t2 < NB * (Cc / 4); t2 += 256) {
        int k = t2 >> 4, c4 = t2 & 15;
        float4 v4 = *(const float4*)(x + ((size_t)(b * Pp) + snn[k]) * Cc + c4 * 4);
        int c = c4 * 4;
        hT[(c + 0) * HT_STRIDE + k] = v4.x;
        hT[(c + 1) * HT_STRIDE + k] = v4.y;
        hT[(c + 2) * HT_STRIDE + k] = v4.z;
        hT[(c + 3) * HT_STRIDE + k] = v4.w;
    }
    for (int t2 = t; t2 < NB * 3; t2 += 256) {
        int k = t2 / 3, d = t2 - 3 * k;
        float cd = (d == 0) ? cx : ((d == 1) ? cy : cz);
        hT[(64 + d) * HT_STRIDE + k] =
            __fsub_rn(pos[((size_t)(b * Pp) + snn[k]) * 3 + d], cd);
    }
    wgbar(barid);

    const float R2A = (float)(0.2 * 0.2);
    const float R2B = (float)(0.4 * 0.4);

    float* outrow = out + (size_t)bm * OUTC;
    run_branch<64, 128, 256>(hT, h1T, sd2s, w2_0, b2_0, w2_1, b2_1,
                             outrow + 128, R2B, t, barid);
    run_branch<32, 64, 128>(hT, h1T, sd2s, w1_0, b1_0, w1_1, b1_1,
                            outrow, R2A, t, barid);
}

// ---------------------------------------------------------------------------
// launch
// ---------------------------------------------------------------------------
extern "C" void kernel_launch(void* const* d_in, const int* in_sizes, int n_in,
                              void* d_out, int out_size)
{
    const float* x    = (const float*)d_in[0];
    const float* pos  = (const float*)d_in[1];
    const float* w1_0 = (const float*)d_in[2];
    const float* b1_0 = (const float*)d_in[3];
    const float* w1_1 = (const float*)d_in[4];
    const float* b1_1 = (const float*)d_in[5];
    const float* w2_0 = (const float*)d_in[6];
    const float* b2_0 = (const float*)d_in[7];
    const float* w2_1 = (const float*)d_in[8];
    const float* b2_1 = (const float*)d_in[9];

    float* out   = (float*)d_out;
    float* pos_s = out + (size_t)Bb * Mm * OUTC;   // [out | pos_s] layout

    // reset progress counters every invocation (graph replay safe)
    void* paddr = nullptr;
    cudaGetSymbolAddress(&paddr, g_progress);
    cudaMemsetAsync(paddr, 0, sizeof(unsigned) * Bb);

    const int smem = 2 * WGF * 4;   // 107520 bytes
    cudaFuncSetAttribute(fused_kernel, cudaFuncAttributeMaxDynamicSharedMemorySize, smem);

    fused_kernel<<<Bb + 2 * Mm, 512, smem>>>(x, pos,
                                             w1_0, b1_0, w1_1, b1_1,
                                             w2_0, b2_0, w2_1, b2_1,
                                             out, pos_s);
}

// round 13
// speedup vs baseline: 1.4363x; 1.4363x over previous
#include <cuda_runtime.h>
#include <math_constants.h>

#define Bb 4
#define Pp 8192
#define Cc 64
#define Mm 2048
#define NB 64
#define OUTC 384
#define HT_STRIDE 68

// per-wg smem floats: union(hT 67*68 + h1T 128*68 = 13260; sd needs 8192) -> 13264 pad
// + sd2 64 + snn 64 + swv/swi 32  -> 13424 -> pad 13440
#define WGF 13440

__device__ unsigned g_progress[Bb];

// ---------------- packed f32x2 helpers (bitwise == two scalar rn ops) -------
typedef unsigned long long u64;

__device__ __forceinline__ u64 pk2(float lo, float hi) {
    u64 r; asm("mov.b64 %0, {%1, %2};" : "=l"(r) : "f"(lo), "f"(hi)); return r;
}
__device__ __forceinline__ void upk2(float& lo, float& hi, u64 v) {
    asm("mov.b64 {%0, %1}, %2;" : "=f"(lo), "=f"(hi) : "l"(v));
}
__device__ __forceinline__ u64 add2(u64 a, u64 b) {
    u64 d; asm("add.rn.f32x2 %0, %1, %2;" : "=l"(d) : "l"(a), "l"(b)); return d;
}
__device__ __forceinline__ u64 mul2(u64 a, u64 b) {
    u64 d; asm("mul.rn.f32x2 %0, %1, %2;" : "=l"(d) : "l"(a), "l"(b)); return d;
}
__device__ __forceinline__ u64 fma2(u64 a, u64 b, u64 c) {
    u64 d; asm("fma.rn.f32x2 %0, %1, %2, %3;" : "=l"(d) : "l"(a), "l"(b), "l"(c)); return d;
}
__device__ __forceinline__ unsigned ld_acq(const unsigned* p) {
    unsigned v; asm volatile("ld.acquire.gpu.global.u32 %0, [%1];" : "=r"(v) : "l"(p)); return v;
}
__device__ __forceinline__ void st_rel(unsigned* p, unsigned v) {
    asm volatile("st.release.gpu.global.u32 [%0], %1;" :: "l"(p), "r"(v) : "memory");
}
__device__ __forceinline__ void wgbar(int id) {
    asm volatile("bar.sync %0, 256;" :: "r"(id) : "memory");
}

// ---------------------------------------------------------------------------
// FPS for one batch, 512 threads (16 points/thread). Bitwise-identical
// selection to the JAX scan. Publishes progress[b] = t+1 after writing ps[t].
// ---------------------------------------------------------------------------
__device__ void fps_block(int b, const float* __restrict__ pos,
                          float* __restrict__ pos_s, unsigned* __restrict__ smu)
{
    const float* pb = pos + (size_t)b * Pp * 3;
    float* ps = pos_s + (size_t)b * Mm * 3;
    const int tid = threadIdx.x;
    const int lane = tid & 31, wrp = tid >> 5;     // 16 warps

    u64 px2[8], py2[8], pz2[8];
    unsigned mind[16];
#pragma unroll
    for (int q = 0; q < 8; q++) {
        int p0 = tid + (2 * q) * 512;
        int p1 = p0 + 512;
        px2[q] = pk2(pb[3 * p0],     pb[3 * p1]);
        py2[q] = pk2(pb[3 * p0 + 1], pb[3 * p1 + 1]);
        pz2[q] = pk2(pb[3 * p0 + 2], pb[3 * p1 + 2]);
    }
#pragma unroll
    for (int i = 0; i < 16; i++) mind[i] = __float_as_uint(1e30f);

    unsigned* swv = smu;         // [2][16]
    unsigned* swi = smu + 32;    // [2][16]

    unsigned sel = 0;
    for (int t = 0; t < Mm; t++) {
        float lx = pb[3 * sel], ly = pb[3 * sel + 1], lz = pb[3 * sel + 2];
        if (tid == 0) {
            ps[3 * t] = lx; ps[3 * t + 1] = ly; ps[3 * t + 2] = lz;
            st_rel(&g_progress[b], (unsigned)(t + 1));
        }

        u64 nx2 = pk2(-lx, -lx);
        u64 ny2 = pk2(-ly, -ly);
        u64 nz2 = pk2(-lz, -lz);

#pragma unroll
        for (int q = 0; q < 8; q++) {
            u64 dx = add2(px2[q], nx2);
            u64 dy = add2(py2[q], ny2);
            u64 dz = add2(pz2[q], nz2);
            u64 s  = add2(add2(mul2(dx, dx), mul2(dy, dy)), mul2(dz, dz));
            float dlo, dhi;
            upk2(dlo, dhi, s);
            mind[2 * q]     = min(mind[2 * q],     __float_as_uint(dlo));
            mind[2 * q + 1] = min(mind[2 * q + 1], __float_as_uint(dhi));
        }
        // 15-op max tree (d2 >= 0 -> uint order == float order)
        unsigned bv;
        {
            unsigned a0 = max(mind[0], mind[1]),  a1 = max(mind[2], mind[3]);
            unsigned a2 = max(mind[4], mind[5]),  a3 = max(mind[6], mind[7]);
            unsigned a4 = max(mind[8], mind[9]),  a5 = max(mind[10], mind[11]);
            unsigned a6 = max(mind[12], mind[13]), a7 = max(mind[14], mind[15]);
            unsigned b0 = max(a0, a1), b1 = max(a2, a3), b2 = max(a4, a5), b3 = max(a6, a7);
            bv = max(max(b0, b1), max(b2, b3));
        }

        unsigned wv = __reduce_max_sync(0xffffffffu, bv);
        unsigned cand = 0xffffffffu;
        if (bv == wv) {
#pragma unroll
            for (int i = 15; i >= 0; i--)
                if (mind[i] == wv) cand = (unsigned)(tid + (i << 9));
        }
        unsigned wi = __reduce_min_sync(0xffffffffu, cand);

        const int buf = (t & 1) * 16;
        if (lane == 0) { swv[buf + wrp] = wv; swi[buf + wrp] = wi; }
        __syncthreads();

        unsigned v  = (lane < 16) ? swv[buf + lane] : 0u;
        unsigned ii = (lane < 16) ? swi[buf + lane] : 0xffffffffu;
        unsigned gv = __reduce_max_sync(0xffffffffu, v);
        unsigned c2 = (v == gv && lane < 16) ? ii : 0xffffffffu;
        sel = __reduce_min_sync(0xffffffffu, c2);
    }
}

// ---------------------------------------------------------------------------
// Branch 2 (K=64, 67->128->256). k-complete warps.
// GEMM1: warp = 64k x 16i, lane = (kk 8)x(ii 4), thread = 8k x 4i.
// GEMM2: warp = 64k x 32j, lane = (kk 8)x(jj 4), thread = 8k x 8j.
// Accumulation order over c/i identical to reference (bitwise).
// ---------------------------------------------------------------------------
__device__ __forceinline__ void branch2(
    const float* __restrict__ hT, float* __restrict__ h1T,
    const float* __restrict__ sd2,
    const float* __restrict__ W1, const float* __restrict__ B1b,
    const float* __restrict__ W2, const float* __restrict__ B2b,
    float* __restrict__ outrow, float r2, int t, int barid)
{
    const int w8 = t >> 5, lane = t & 31;
    const int kk = lane >> 2;
    const int kbase = kk * 8;

    // ---- GEMM1 ----
    {
        const int ii = lane & 3;
        const int ibase = w8 * 16 + ii * 4;

        u64 acc[8][2];
#pragma unroll
        for (int v = 0; v < 8; v++) { acc[v][0] = 0ull; acc[v][1] = 0ull; }

        for (int c = 0; c < 67; c++) {
            float4 a0 = *(const float4*)(hT + c * HT_STRIDE + kbase);
            float4 a1 = *(const float4*)(hT + c * HT_STRIDE + kbase + 4);
            float4 wv = *(const float4*)(W1 + c * 128 + ibase);
            u64 wb0 = pk2(wv.x, wv.y), wb1 = pk2(wv.z, wv.w);
            float a[8] = {a0.x, a0.y, a0.z, a0.w, a1.x, a1.y, a1.z, a1.w};
#pragma unroll
            for (int v = 0; v < 8; v++) {
                u64 av = pk2(a[v], a[v]);
                acc[v][0] = fma2(av, wb0, acc[v][0]);
                acc[v][1] = fma2(av, wb1, acc[v][1]);
            }
        }
        float bias[4];
#pragma unroll
        for (int u = 0; u < 4; u++) bias[u] = B1b[ibase + u];
#pragma unroll
        for (int u = 0; u < 4; u++) {
            float r[8];
#pragma unroll
            for (int v = 0; v < 8; v++) {
                float lo, hi;
                upk2(lo, hi, acc[v][u >> 1]);
                float val = (u & 1) ? hi : lo;
                r[v] = fmaxf(val + bias[u], 0.f);
            }
            float4 v0 = {r[0], r[1], r[2], r[3]};
            float4 v1 = {r[4], r[5], r[6], r[7]};
            *(float4*)(h1T + (ibase + u) * HT_STRIDE + kbase)     = v0;
            *(float4*)(h1T + (ibase + u) * HT_STRIDE + kbase + 4) = v1;
        }
    }
    wgbar(barid);

    // ---- GEMM2 + masked max ----
    {
        const int jj = lane & 3;
        const int jbase = w8 * 32 + jj * 8;

        u64 acc[8][4];
#pragma unroll
        for (int v = 0; v < 8; v++)
#pragma unroll
            for (int p = 0; p < 4; p++) acc[v][p] = 0ull;

        for (int i = 0; i < 128; i++) {
            float4 a0 = *(const float4*)(h1T + i * HT_STRIDE + kbase);
            float4 a1 = *(const float4*)(h1T + i * HT_STRIDE + kbase + 4);
            float4 w0 = *(const float4*)(W2 + i * 256 + jbase);
            float4 w1 = *(const float4*)(W2 + i * 256 + jbase + 4);
            u64 wb[4] = {pk2(w0.x, w0.y), pk2(w0.z, w0.w),
                         pk2(w1.x, w1.y), pk2(w1.z, w1.w)};
            float a[8] = {a0.x, a0.y, a0.z, a0.w, a1.x, a1.y, a1.z, a1.w};
#pragma unroll
            for (int v = 0; v < 8; v++) {
                u64 av = pk2(a[v], a[v]);
#pragma unroll
                for (int p = 0; p < 4; p++)
                    acc[v][p] = fma2(av, wb[p], acc[v][p]);
            }
        }

        float4 s0 = *(const float4*)(sd2 + kbase);
        float4 s1 = *(const float4*)(sd2 + kbase + 4);
        float sdk[8] = {s0.x, s0.y, s0.z, s0.w, s1.x, s1.y, s1.z, s1.w};
        float mx[8];
#pragma unroll
        for (int p = 0; p < 4; p++) {
            float blo = B2b[jbase + 2 * p], bhi = B2b[jbase + 2 * p + 1];
            float mlo = -1e30f, mhi = -1e30f;
#pragma unroll
            for (int v = 0; v < 8; v++) {
                float lo, hi;
                upk2(lo, hi, acc[v][p]);
                float vlo = fmaxf(lo + blo, 0.f);
                float vhi = fmaxf(hi + bhi, 0.f);
                if (!(sdk[v] <= r2)) { vlo = -1e30f; vhi = -1e30f; }
                mlo = fmaxf(mlo, vlo);
                mhi = fmaxf(mhi, vhi);
            }
            mx[2 * p] = mlo; mx[2 * p + 1] = mhi;
        }
        // butterfly max across kk (lane bits 2..4); fp max exact (no NaN)
#pragma unroll
        for (int off = 4; off <= 16; off <<= 1)
#pragma unroll
            for (int u = 0; u < 8; u++)
                mx[u] = fmaxf(mx[u], __shfl_xor_sync(0xffffffffu, mx[u], off));
        if (kk == 0) {
            float4 o0 = {mx[0], mx[1], mx[2], mx[3]};
            float4 o1 = {mx[4], mx[5], mx[6], mx[7]};
            *(float4*)(outrow + jbase)     = o0;
            *(float4*)(outrow + jbase + 4) = o1;
        }
    }
}

// ---------------------------------------------------------------------------
// Branch 1 (K=32, 67->64->128). k-complete warps.
// GEMM1: warp = 32k x 8i, lane = (kk 4)x(ii 8), thread = 8k x 1i.
// GEMM2: warp = 32k x 16j, lane = (kk 4)x(jj 8), thread = 8k x 2j.
// ---------------------------------------------------------------------------
__device__ __forceinline__ void branch1(
    const float* __restrict__ hT, float* __restrict__ h1T,
    const float* __restrict__ sd2,
    const float* __restrict__ W1, const float* __restrict__ B1b,
    const float* __restrict__ W2, const float* __restrict__ B2b,
    float* __restrict__ outrow, float r2, int t, int barid)
{
    const int w8 = t >> 5, lane = t & 31;
    const int kk = lane >> 3;
    const int kbase = kk * 8;

    // ---- GEMM1 ----
    {
        const int ii = lane & 7;
        const int ibase = w8 * 8 + ii;

        float acc[8];
#pragma unroll
        for (int v = 0; v < 8; v++) acc[v] = 0.f;

        for (int c = 0; c < 67; c++) {
            float4 a0 = *(const float4*)(hT + c * HT_STRIDE + kbase);
            float4 a1 = *(const float4*)(hT + c * HT_STRIDE + kbase + 4);
            float wv = W1[c * 64 + ibase];
            float a[8] = {a0.x, a0.y, a0.z, a0.w, a1.x, a1.y, a1.z, a1.w};
#pragma unroll
            for (int v = 0; v < 8; v++) acc[v] = fmaf(a[v], wv, acc[v]);
        }
        float bias = B1b[ibase];
        float r[8];
#pragma unroll
        for (int v = 0; v < 8; v++) r[v] = fmaxf(acc[v] + bias, 0.f);
        float4 v0 = {r[0], r[1], r[2], r[3]};
        float4 v1 = {r[4], r[5], r[6], r[7]};
        *(float4*)(h1T + ibase * HT_STRIDE + kbase)     = v0;
        *(float4*)(h1T + ibase * HT_STRIDE + kbase + 4) = v1;
    }
    wgbar(barid);

    // ---- GEMM2 + masked max ----
    {
        const int jj = lane & 7;
        const int jbase = w8 * 16 + jj * 2;

        u64 acc[8];
#pragma unroll
        for (int v = 0; v < 8; v++) acc[v] = 0ull;

        for (int i = 0; i < 64; i++) {
            float4 a0 = *(const float4*)(h1T + i * HT_STRIDE + kbase);
            float4 a1 = *(const float4*)(h1T + i * HT_STRIDE + kbase + 4);
            float2 wv = *(const float2*)(W2 + i * 128 + jbase);
            u64 wb = pk2(wv.x, wv.y);
            float a[8] = {a0.x, a0.y, a0.z, a0.w, a1.x, a1.y, a1.z, a1.w};
#pragma unroll
            for (int v = 0; v < 8; v++) {
                u64 av = pk2(a[v], a[v]);
                acc[v] = fma2(av, wb, acc[v]);
            }
        }

        float4 s0 = *(const float4*)(sd2 + kbase);
        float4 s1 = *(const float4*)(sd2 + kbase + 4);
        float sdk[8] = {s0.x, s0.y, s0.z, s0.w, s1.x, s1.y, s1.z, s1.w};
        float blo = B2b[jbase], bhi = B2b[jbase + 1];
        float mlo = -1e30f, mhi = -1e30f;
#pragma unroll
        for (int v = 0; v < 8; v++) {
            float lo, hi;
            upk2(lo, hi, acc[v]);
            float vlo = fmaxf(lo + blo, 0.f);
            float vhi = fmaxf(hi + bhi, 0.f);
            if (!(sdk[v] <= r2)) { vlo = -1e30f; vhi = -1e30f; }
            mlo = fmaxf(mlo, vlo);
            mhi = fmaxf(mhi, vhi);
        }
        // butterfly max across kk (lane bits 3..4)
#pragma unroll
        for (int off = 8; off <= 16; off <<= 1) {
            mlo = fmaxf(mlo, __shfl_xor_sync(0xffffffffu, mlo, off));
            mhi = fmaxf(mhi, __shfl_xor_sync(0xffffffffu, mhi, off));
        }
        if (kk == 0) {
            float2 o = {mlo, mhi};
            *(float2*)(outrow + jbase) = o;
        }
    }
}

// ---------------------------------------------------------------------------
// Fused kernel: blocks 0..3 = FPS; blocks 4.. = workers (2 sub-units x 256thr,
// each doing KNN + MLP for one centroid, spin-waiting on FPS progress).
// ---------------------------------------------------------------------------
__global__ void __launch_bounds__(512, 1) fused_kernel(
    const float* __restrict__ x, const float* __restrict__ pos,
    const float* __restrict__ w1_0, const float* __restrict__ b1_0,
    const float* __restrict__ w1_1, const float* __restrict__ b1_1,
    const float* __restrict__ w2_0, const float* __restrict__ b2_0,
    const float* __restrict__ w2_1, const float* __restrict__ b2_1,
    float* __restrict__ out, float* __restrict__ pos_s)
{
    extern __shared__ float sm[];

    if (blockIdx.x < Bb) {
        fps_block(blockIdx.x, pos, pos_s, (unsigned*)sm);
        return;
    }

    const int w  = blockIdx.x - Bb;
    const int wg = threadIdx.x >> 8;          // 0..1
    const int t  = threadIdx.x & 255;
    const int barid = wg + 1;
    const int b  = 2 * (w & 1) + wg;
    const int m  = w >> 1;
    const int bm = b * Mm + m;
    const int lane = t & 31, w8 = t >> 5;

    float*    base = sm + wg * WGF;
    float*    un   = base;                    // union: sd[8192] / hT+h1T[13260]
    float*    sd2s = base + 13264;            // 64
    int*      snn  = (int*)(base + 13328);    // 64
    unsigned* swv  = (unsigned*)(base + 13392);  // [2][8]
    unsigned* swi  = swv + 16;                   // [2][8]

    // ---- wait for our centroid ----
    if (t == 0) {
        while (ld_acq(&g_progress[b]) <= (unsigned)m) __nanosleep(128);
    }
    wgbar(barid);

    const float cx = pos_s[bm * 3], cy = pos_s[bm * 3 + 1], cz = pos_s[bm * 3 + 2];
    const float* pb = pos + (size_t)b * Pp * 3;

    // ---- KNN: distances (packed, bitwise == scalar rn) ----
    float* sd = un;
    unsigned lv = 0x7f800000u, li = 0xffffffffu;
    {
        u64 c2x = pk2(cx, cx), c2y = pk2(cy, cy), c2z = pk2(cz, cz);
        const u64 SMASK = 0x8000000080000000ull;
#pragma unroll 4
        for (int q = 0; q < 16; q++) {
            int p0 = t + (2 * q) * 256;
            int p1 = p0 + 256;
            u64 X = pk2(pb[3 * p0],     pb[3 * p1]);
            u64 Y = pk2(pb[3 * p0 + 1], pb[3 * p1 + 1]);
            u64 Z = pk2(pb[3 * p0 + 2], pb[3 * p1 + 2]);
            u64 dx = add2(c2x, X ^ SMASK);    // cx + (-px) == cx - px (rn exact)
            u64 dy = add2(c2y, Y ^ SMASK);
            u64 dz = add2(c2z, Z ^ SMASK);
            u64 s  = add2(add2(mul2(dx, dx), mul2(dy, dy)), mul2(dz, dz));
            float dlo, dhi;
            upk2(dlo, dhi, s);
            sd[p0] = dlo; sd[p1] = dhi;
            unsigned v0 = __float_as_uint(dlo), v1 = __float_as_uint(dhi);
            if (v0 < lv) { lv = v0; li = (unsigned)p0; }
            if (v1 < lv) { lv = v1; li = (unsigned)p1; }
        }
    }
    wgbar(barid);

    // ---- KNN: 64 rounds of block argmin (value, then lowest index) ----
    for (int r = 0; r < NB; r++) {
        unsigned wv = __reduce_min_sync(0xffffffffu, lv);
        unsigned cand = (lv == wv) ? li : 0xffffffffu;
        unsigned wi = __reduce_min_sync(0xffffffffu, cand);
        const int buf = (r & 1) * 8;
        if (lane == 0) { swv[buf + w8] = wv; swi[buf + w8] = wi; }
        wgbar(barid);
        unsigned v  = (lane < 8) ? swv[buf + lane] : 0xffffffffu;
        unsigned ii = (lane < 8) ? swi[buf + lane] : 0xffffffffu;
        unsigned gv = __reduce_min_sync(0xffffffffu, v);
        unsigned c2 = (v == gv && lane < 8) ? ii : 0xffffffffu;
        unsigned gi = __reduce_min_sync(0xffffffffu, c2);
        if (t == 0) { snn[r] = (int)gi; sd2s[r] = __uint_as_float(gv); }
        unsigned ot = gi & 255u;                 // owner thread in wg
        if ((unsigned)w8 == (ot >> 5)) {         // owner warp: cooperative rescan
            if ((unsigned)t == ot) sd[gi] = CUDART_INF_F;
            __syncwarp();
            unsigned pp = ot + (unsigned)lane * 256u;
            unsigned vv = __float_as_uint(sd[pp]);
            unsigned mv = __reduce_min_sync(0xffffffffu, vv);
            unsigned mc = (vv == mv) ? pp : 0xffffffffu;
            unsigned mi = __reduce_min_sync(0xffffffffu, mc);
            if ((unsigned)t == ot) { lv = mv; li = mi; }
        }
    }
    wgbar(barid);

    // ---- gather hT (overwrites sd region; all KNN reads done) ----
    float* hT  = un;
    float* h1T = un + 67 * HT_STRIDE;
    for (int t2 = t; t2 < NB * (Cc / 4); t2 += 256) {
        int k = t2 >> 4, c4 = t2 & 15;
        float4 v4 = *(const float4*)(x + ((size_t)(b * Pp) + snn[k]) * Cc + c4 * 4);
        int c = c4 * 4;
        hT[(c + 0) * HT_STRIDE + k] = v4.x;
        hT[(c + 1) * HT_STRIDE + k] = v4.y;
        hT[(c + 2) * HT_STRIDE + k] = v4.z;
        hT[(c + 3) * HT_STRIDE + k] = v4.w;
    }
    for (int t2 = t; t2 < NB * 3; t2 += 256) {
        int k = t2 / 3, d = t2 - 3 * k;
        float cd = (d == 0) ? cx : ((d == 1) ? cy : cz);
        hT[(64 + d) * HT_STRIDE + k] =
            __fsub_rn(pos[((size_t)(b * Pp) + snn[k]) * 3 + d], cd);
    }
    wgbar(barid);

    const float R2A = (float)(0.2 * 0.2);
    const float R2B = (float)(0.4 * 0.4);

    float* outrow = out + (size_t)bm * OUTC;
    // branch 2: K=64, 67->128->256, output channels [128,384)
    branch2(hT, h1T, sd2s, w2_0, b2_0, w2_1, b2_1, outrow + 128, R2B, t, barid);
    wgbar(barid);   // b2's h1T reads complete before b1 overwrites h1T
    // branch 1: K=32 (prefix of sorted 64-NN), 67->64->128, channels [0,128)
    branch1(hT, h1T, sd2s, w1_0, b1_0, w1_1, b1_1, outrow, R2A, t, barid);
}

// ---------------------------------------------------------------------------
// launch
// ---------------------------------------------------------------------------
extern "C" void kernel_launch(void* const* d_in, const int* in_sizes, int n_in,
                              void* d_out, int out_size)
{
    const float* x    = (const float*)d_in[0];
    const float* pos  = (const float*)d_in[1];
    const float* w1_0 = (const float*)d_in[2];
    const float* b1_0 = (const float*)d_in[3];
    const float* w1_1 = (const float*)d_in[4];
    const float* b1_1 = (const float*)d_in[5];
    const float* w2_0 = (const float*)d_in[6];
    const float* b2_0 = (const float*)d_in[7];
    const float* w2_1 = (const float*)d_in[8];
    const float* b2_1 = (const float*)d_in[9];

    float* out   = (float*)d_out;
    float* pos_s = out + (size_t)Bb * Mm * OUTC;   // [out | pos_s] layout

    // reset progress counters every invocation (graph replay safe)
    void* paddr = nullptr;
    cudaGetSymbolAddress(&paddr, g_progress);
    cudaMemsetAsync(paddr, 0, sizeof(unsigned) * Bb);

    const int smem = 2 * WGF * 4;   // 107520 bytes
    cudaFuncSetAttribute(fused_kernel, cudaFuncAttributeMaxDynamicSharedMemorySize, smem);

    fused_kernel<<<Bb + 2 * Mm, 512, smem>>>(x, pos,
                                             w1_0, b1_0, w1_1, b1_1,
                                             w2_0, b2_0, w2_1, b2_1,
                                             out, pos_s);
}

// round 14
// speedup vs baseline: 1.5255x; 1.0621x over previous
#include <cuda_runtime.h>
#include <math_constants.h>

#define Bb 4
#define Pp 8192
#define Cc 64
#define Mm 2048
#define NB 64
#define OUTC 384
#define HT_STRIDE 68

// per-wg smem floats: union(hT 67*68 + h1T 128*68 = 13260; sd needs 8192) -> 13264 pad
// + sd2 64 + snn 64 + swv/swi 32  -> 13424 -> pad 13440
#define WGF 13440

__device__ unsigned g_progress[Bb];

// ---------------- packed f32x2 helpers (bitwise == two scalar rn ops) -------
typedef unsigned long long u64;

__device__ __forceinline__ u64 pk2(float lo, float hi) {
    u64 r; asm("mov.b64 %0, {%1, %2};" : "=l"(r) : "f"(lo), "f"(hi)); return r;
}
__device__ __forceinline__ void upk2(float& lo, float& hi, u64 v) {
    asm("mov.b64 {%0, %1}, %2;" : "=f"(lo), "=f"(hi) : "l"(v));
}
__device__ __forceinline__ u64 add2(u64 a, u64 b) {
    u64 d; asm("add.rn.f32x2 %0, %1, %2;" : "=l"(d) : "l"(a), "l"(b)); return d;
}
__device__ __forceinline__ u64 mul2(u64 a, u64 b) {
    u64 d; asm("mul.rn.f32x2 %0, %1, %2;" : "=l"(d) : "l"(a), "l"(b)); return d;
}
__device__ __forceinline__ u64 fma2(u64 a, u64 b, u64 c) {
    u64 d; asm("fma.rn.f32x2 %0, %1, %2, %3;" : "=l"(d) : "l"(a), "l"(b), "l"(c)); return d;
}
__device__ __forceinline__ unsigned ld_acq(const unsigned* p) {
    unsigned v; asm volatile("ld.acquire.gpu.global.u32 %0, [%1];" : "=r"(v) : "l"(p)); return v;
}
__device__ __forceinline__ void st_rel(unsigned* p, unsigned v) {
    asm volatile("st.release.gpu.global.u32 [%0], %1;" :: "l"(p), "r"(v) : "memory");
}
__device__ __forceinline__ void wgbar(int id) {
    asm volatile("bar.sync %0, 256;" :: "r"(id) : "memory");
}
// weights: keep resident in L1 across wg iterations
__device__ __forceinline__ float4 ldw4(const float* p) {
    float4 v;
    asm("ld.global.nc.L1::evict_last.v4.f32 {%0,%1,%2,%3}, [%4];"
        : "=f"(v.x), "=f"(v.y), "=f"(v.z), "=f"(v.w) : "l"(p));
    return v;
}
__device__ __forceinline__ float2 ldw2v(const float* p) {
    float2 v;
    asm("ld.global.nc.L1::evict_last.v2.f32 {%0,%1}, [%2];"
        : "=f"(v.x), "=f"(v.y) : "l"(p));
    return v;
}
// one-shot gather: don't pollute L1
__device__ __forceinline__ float4 ldx4(const float* p) {
    float4 v;
    asm("ld.global.nc.L1::evict_first.v4.f32 {%0,%1,%2,%3}, [%4];"
        : "=f"(v.x), "=f"(v.y), "=f"(v.z), "=f"(v.w) : "l"(p));
    return v;
}

// ---------------------------------------------------------------------------
// FPS for one batch, 512 threads (16 points/thread). Bitwise-identical
// selection to the JAX scan. Publishes progress[b] = t+1 after writing ps[t].
// ---------------------------------------------------------------------------
__device__ void fps_block(int b, const float* __restrict__ pos,
                          float* __restrict__ pos_s, unsigned* __restrict__ smu)
{
    const float* pb = pos + (size_t)b * Pp * 3;
    float* ps = pos_s + (size_t)b * Mm * 3;
    const int tid = threadIdx.x;
    const int lane = tid & 31, wrp = tid >> 5;     // 16 warps

    u64 px2[8], py2[8], pz2[8];
    unsigned mind[16];
#pragma unroll
    for (int q = 0; q < 8; q++) {
        int p0 = tid + (2 * q) * 512;
        int p1 = p0 + 512;
        px2[q] = pk2(pb[3 * p0],     pb[3 * p1]);
        py2[q] = pk2(pb[3 * p0 + 1], pb[3 * p1 + 1]);
        pz2[q] = pk2(pb[3 * p0 + 2], pb[3 * p1 + 2]);
    }
#pragma unroll
    for (int i = 0; i < 16; i++) mind[i] = __float_as_uint(1e30f);

    unsigned* swv = smu;         // [2][16]
    unsigned* swi = smu + 32;    // [2][16]

    unsigned sel = 0;
    for (int t = 0; t < Mm; t++) {
        float lx = pb[3 * sel], ly = pb[3 * sel + 1], lz = pb[3 * sel + 2];
        if (tid == 0) {
            ps[3 * t] = lx; ps[3 * t + 1] = ly; ps[3 * t + 2] = lz;
            st_rel(&g_progress[b], (unsigned)(t + 1));
        }

        u64 nx2 = pk2(-lx, -lx);
        u64 ny2 = pk2(-ly, -ly);
        u64 nz2 = pk2(-lz, -lz);

#pragma unroll
        for (int q = 0; q < 8; q++) {
            u64 dx = add2(px2[q], nx2);
            u64 dy = add2(py2[q], ny2);
            u64 dz = add2(pz2[q], nz2);
            u64 s  = add2(add2(mul2(dx, dx), mul2(dy, dy)), mul2(dz, dz));
            float dlo, dhi;
            upk2(dlo, dhi, s);
            mind[2 * q]     = min(mind[2 * q],     __float_as_uint(dlo));
            mind[2 * q + 1] = min(mind[2 * q + 1], __float_as_uint(dhi));
        }
        // 15-op max tree (d2 >= 0 -> uint order == float order)
        unsigned bv;
        {
            unsigned a0 = max(mind[0], mind[1]),  a1 = max(mind[2], mind[3]);
            unsigned a2 = max(mind[4], mind[5]),  a3 = max(mind[6], mind[7]);
            unsigned a4 = max(mind[8], mind[9]),  a5 = max(mind[10], mind[11]);
            unsigned a6 = max(mind[12], mind[13]), a7 = max(mind[14], mind[15]);
            unsigned b0 = max(a0, a1), b1 = max(a2, a3), b2 = max(a4, a5), b3 = max(a6, a7);
            bv = max(max(b0, b1), max(b2, b3));
        }

        unsigned wv = __reduce_max_sync(0xffffffffu, bv);
        unsigned cand = 0xffffffffu;
        if (bv == wv) {
#pragma unroll
            for (int i = 15; i >= 0; i--)
                if (mind[i] == wv) cand = (unsigned)(tid + (i << 9));
        }
        unsigned wi = __reduce_min_sync(0xffffffffu, cand);

        const int buf = (t & 1) * 16;
        if (lane == 0) { swv[buf + wrp] = wv; swi[buf + wrp] = wi; }
        __syncthreads();

        unsigned v  = (lane < 16) ? swv[buf + lane] : 0u;
        unsigned ii = (lane < 16) ? swi[buf + lane] : 0xffffffffu;
        unsigned gv = __reduce_max_sync(0xffffffffu, v);
        unsigned c2 = (v == gv && lane < 16) ? ii : 0xffffffffu;
        sel = __reduce_min_sync(0xffffffffu, c2);
    }
}

// ---------------------------------------------------------------------------
// per-centroid MLP branch (R10 mapping, block-wide barriers for phase-lock).
// Block 256-thread sub-unit does compute; barriers are __syncthreads() so the
// two sub-units stream identical weight lines together (L1/L2 reuse).
// ---------------------------------------------------------------------------
template<int K, int H1, int H2>
__device__ __forceinline__ void run_branch(
    const float* __restrict__ hT, float* __restrict__ h1T,
    const float* __restrict__ sd2,
    const float* __restrict__ W1, const float* __restrict__ B1b,
    const float* __restrict__ W2, const float* __restrict__ B2b,
    float* __restrict__ outrow, float r2, int tx, int ty, int t)
{
    constexpr int KV = K / 8;     // neighbors per thread
    constexpr int IU = H1 / 32;   // hidden1 channels per thread
    constexpr int JU = H2 / 32;   // hidden2 channels per thread
    constexpr int IU2 = IU / 2, JU2 = JU / 2;
    constexpr bool SPLIT = (JU == 8);   // split channel halves for 16B/lane LDG

    // ---- GEMM1: h1[i][k] = relu(sum_c hT[c][k]*W1[c][i] + b1[i]) ----
    {
        u64 acc[KV][IU2];
#pragma unroll
        for (int v = 0; v < KV; v++)
#pragma unroll
            for (int u = 0; u < IU2; u++) acc[v][u] = 0ull;

        auto lda = [&](float* a, int c) {
            const float4* hp = (const float4*)(hT + c * HT_STRIDE + ty * KV);
#pragma unroll
            for (int q = 0; q < KV / 4; q++) {
                float4 t4 = hp[q];
                a[4*q] = t4.x; a[4*q+1] = t4.y; a[4*q+2] = t4.z; a[4*q+3] = t4.w;
            }
        };
        auto ldw = [&](u64* bb, int c) {
            const float* wp = W1 + c * H1 + tx * IU;
            if constexpr (IU == 4) {
                float4 t4 = ldw4(wp);
                bb[0] = pk2(t4.x, t4.y); bb[1] = pk2(t4.z, t4.w);
            } else {
                float2 t2 = ldw2v(wp);
                bb[0] = pk2(t2.x, t2.y);
            }
        };
        auto body = [&](const float* a, const u64* bb) {
#pragma unroll
            for (int v = 0; v < KV; v++) {
                u64 av = pk2(a[v], a[v]);
#pragma unroll
                for (int u = 0; u < IU2; u++)
                    acc[v][u] = fma2(av, bb[u], acc[v][u]);
            }
        };

        for (int c = 0; c < 66; c += 2) {
            u64 bb0[IU2], bb1[IU2];
            float a0[KV], a1[KV];
            ldw(bb0, c); ldw(bb1, c + 1);        // batched LDGs first
            lda(a0, c);  lda(a1, c + 1);
            body(a0, bb0);
            body(a1, bb1);
        }
        {   // tail c = 66
            u64 bbt[IU2]; float at[KV];
            ldw(bbt, 66); lda(at, 66);
            body(at, bbt);
        }

        float bias[IU];
#pragma unroll
        for (int u = 0; u < IU; u++) bias[u] = B1b[tx * IU + u];
#pragma unroll
        for (int u = 0; u < IU2; u++) {
#pragma unroll
            for (int v = 0; v < KV; v++) {
                float lo, hi;
                upk2(lo, hi, acc[v][u]);
                int i0 = tx * IU + 2 * u;
                int k  = ty * KV + v;
                h1T[i0 * HT_STRIDE + k]       = fmaxf(lo + bias[2*u],     0.f);
                h1T[(i0 + 1) * HT_STRIDE + k] = fmaxf(hi + bias[2*u + 1], 0.f);
            }
        }
    }
    __syncthreads();

    // ---- GEMM2 + masked max over k ----
    {
        u64 acc[KV][JU2];
#pragma unroll
        for (int v = 0; v < KV; v++)
#pragma unroll
            for (int u = 0; u < JU2; u++) acc[v][u] = 0ull;

        auto ldw2 = [&](u64* bb, int i) {
            if constexpr (SPLIT) {
                float4 tA = ldw4(W2 + i * H2 + tx * 4);
                float4 tB = ldw4(W2 + i * H2 + H2 / 2 + tx * 4);
                bb[0] = pk2(tA.x, tA.y); bb[1] = pk2(tA.z, tA.w);
                bb[2] = pk2(tB.x, tB.y); bb[3] = pk2(tB.z, tB.w);
            } else {
                float4 t4 = ldw4(W2 + i * H2 + tx * 4);
                bb[0] = pk2(t4.x, t4.y); bb[1] = pk2(t4.z, t4.w);
            }
        };
        auto lda2 = [&](float* a, int i) {
            const float4* hp = (const float4*)(h1T + i * HT_STRIDE + ty * KV);
#pragma unroll
            for (int q = 0; q < KV / 4; q++) {
                float4 t4 = hp[q];
                a[4*q] = t4.x; a[4*q+1] = t4.y; a[4*q+2] = t4.z; a[4*q+3] = t4.w;
            }
        };
        auto body2 = [&](const float* a, const u64* bb) {
#pragma unroll
            for (int v = 0; v < KV; v++) {
                u64 av = pk2(a[v], a[v]);
#pragma unroll
                for (int u = 0; u < JU2; u++)
                    acc[v][u] = fma2(av, bb[u], acc[v][u]);
            }
        };

        for (int i = 0; i < H1; i += 2) {
            u64 bb0[JU2], bb1[JU2];
            float a0[KV], a1[KV];
            ldw2(bb0, i); ldw2(bb1, i + 1);      // batched LDGs first
            lda2(a0, i);  lda2(a1, i + 1);
            body2(a0, bb0);
            body2(a1, bb1);
        }

        // channel index for mx[u]
        auto CH = [&](int u) -> int {
            if constexpr (SPLIT) return (u < 4) ? (tx * 4 + u) : (H2 / 2 + tx * 4 + (u - 4));
            else                 return tx * 4 + u;
        };

        float b2[JU];
#pragma unroll
        for (int u = 0; u < JU; u++) b2[u] = B2b[CH(u)];
        float mx[JU];
#pragma unroll
        for (int u = 0; u < JU; u++) mx[u] = -1e30f;
#pragma unroll
        for (int v = 0; v < KV; v++) {
            bool ok = (sd2[ty * KV + v] <= r2);
#pragma unroll
            for (int u = 0; u < JU2; u++) {
                float lo, hi;
                upk2(lo, hi, acc[v][u]);
                float v0 = fmaxf(lo + b2[2*u],     0.f);
                float v1 = fmaxf(hi + b2[2*u + 1], 0.f);
                if (!ok) { v0 = -1e30f; v1 = -1e30f; }
                mx[2*u]     = fmaxf(mx[2*u],     v0);
                mx[2*u + 1] = fmaxf(mx[2*u + 1], v1);
            }
        }

        // red aliases h1T: all h1T reads are done (acc complete), sync then reuse
        __syncthreads();
        float* red = h1T;   // 8 * H2 <= 2048 floats, fits in h1T region
#pragma unroll
        for (int u = 0; u < JU; u++) red[ty * H2 + CH(u)] = mx[u];
        __syncthreads();
        for (int j = t; j < H2; j += 256) {
            float mm = red[j];
#pragma unroll
            for (int w = 1; w < 8; w++) mm = fmaxf(mm, red[w * H2 + j]);
            outrow[j] = mm;
        }
        __syncthreads();
    }
}

// ---------------------------------------------------------------------------
// Fused kernel: blocks 0..3 = FPS; blocks 4.. = workers (2 sub-units x 256thr,
// SAME batch, adjacent centroids m and m+1 -> shared pos/weight streams).
// ---------------------------------------------------------------------------
__global__ void __launch_bounds__(512, 1) fused_kernel(
    const float* __restrict__ x, const float* __restrict__ pos,
    const float* __restrict__ w1_0, const float* __restrict__ b1_0,
    const float* __restrict__ w1_1, const float* __restrict__ b1_1,
    const float* __restrict__ w2_0, const float* __restrict__ b2_0,
    const float* __restrict__ w2_1, const float* __restrict__ b2_1,
    float* __restrict__ out, float* __restrict__ pos_s)
{
    extern __shared__ float sm[];

    if (blockIdx.x < Bb) {
        fps_block(blockIdx.x, pos, pos_s, (unsigned*)sm);
        return;
    }

    const int w  = blockIdx.x - Bb;
    const int wg = threadIdx.x >> 8;          // 0..1
    const int t  = threadIdx.x & 255;
    const int barid = wg + 1;
    const int b  = w & 3;                     // same batch for both wgs
    const int m  = (w >> 2) * 2 + wg;         // adjacent centroids
    const int bm = b * Mm + m;
    const int lane = t & 31, w8 = t >> 5;

    float*    base = sm + wg * WGF;
    float*    un   = base;                    // union: sd[8192] / hT+h1T[13260]
    float*    sd2s = base + 13264;            // 64
    int*      snn  = (int*)(base + 13328);    // 64
    unsigned* swv  = (unsigned*)(base + 13392);  // [2][8]
    unsigned* swi  = swv + 16;                   // [2][8]

    // ---- wait for our centroid ----
    if (t == 0) {
        while (ld_acq(&g_progress[b]) <= (unsigned)m) __nanosleep(128);
    }
    wgbar(barid);

    const float cx = pos_s[bm * 3], cy = pos_s[bm * 3 + 1], cz = pos_s[bm * 3 + 2];
    const float* pb = pos + (size_t)b * Pp * 3;

    // ---- KNN: distances (packed, bitwise == scalar rn) ----
    float* sd = un;
    unsigned lv = 0x7f800000u, li = 0xffffffffu;
    {
        u64 c2x = pk2(cx, cx), c2y = pk2(cy, cy), c2z = pk2(cz, cz);
        const u64 SMASK = 0x8000000080000000ull;
#pragma unroll 4
        for (int q = 0; q < 16; q++) {
            int p0 = t + (2 * q) * 256;
            int p1 = p0 + 256;
            u64 X = pk2(pb[3 * p0],     pb[3 * p1]);
            u64 Y = pk2(pb[3 * p0 + 1], pb[3 * p1 + 1]);
            u64 Z = pk2(pb[3 * p0 + 2], pb[3 * p1 + 2]);
            u64 dx = add2(c2x, X ^ SMASK);    // cx + (-px) == cx - px (rn exact)
            u64 dy = add2(c2y, Y ^ SMASK);
            u64 dz = add2(c2z, Z ^ SMASK);
            u64 s  = add2(add2(mul2(dx, dx), mul2(dy, dy)), mul2(dz, dz));
            float dlo, dhi;
            upk2(dlo, dhi, s);
            sd[p0] = dlo; sd[p1] = dhi;
            unsigned v0 = __float_as_uint(dlo), v1 = __float_as_uint(dhi);
            if (v0 < lv) { lv = v0; li = (unsigned)p0; }
            if (v1 < lv) { lv = v1; li = (unsigned)p1; }
        }
    }
    wgbar(barid);

    // ---- KNN: 64 rounds of block argmin (value, then lowest index) ----
    for (int r = 0; r < NB; r++) {
        unsigned wv = __reduce_min_sync(0xffffffffu, lv);
        unsigned cand = (lv == wv) ? li : 0xffffffffu;
        unsigned wi = __reduce_min_sync(0xffffffffu, cand);
        const int buf = (r & 1) * 8;
        if (lane == 0) { swv[buf + w8] = wv; swi[buf + w8] = wi; }
        wgbar(barid);
        unsigned v  = (lane < 8) ? swv[buf + lane] : 0xffffffffu;
        unsigned ii = (lane < 8) ? swi[buf + lane] : 0xffffffffu;
        unsigned gv = __reduce_min_sync(0xffffffffu, v);
        unsigned c2 = (v == gv && lane < 8) ? ii : 0xffffffffu;
        unsigned gi = __reduce_min_sync(0xffffffffu, c2);
        if (t == 0) { snn[r] = (int)gi; sd2s[r] = __uint_as_float(gv); }
        unsigned ot = gi & 255u;                 // owner thread in wg
        if ((unsigned)w8 == (ot >> 5)) {         // owner warp: cooperative rescan
            if ((unsigned)t == ot) sd[gi] = CUDART_INF_F;
            __syncwarp();
            unsigned pp = ot + (unsigned)lane * 256u;
            unsigned vv = __float_as_uint(sd[pp]);
            unsigned mv = __reduce_min_sync(0xffffffffu, vv);
            unsigned mc = (vv == mv) ? pp : 0xffffffffu;
            unsigned mi = __reduce_min_sync(0xffffffffu, mc);
            if ((unsigned)t == ot) { lv = mv; li = mi; }
        }
    }
    wgbar(barid);

    // ---- gather hT (overwrites sd region; all KNN reads done) ----
    float* hT  = un;
    float* h1T = un + 67 * HT_STRIDE;
    for (int t2 = t; t2 < NB * (Cc / 4); t2 += 256) {
        int k = t2 >> 4, c4 = t2 & 15;
        float4 v4 = ldx4(x + ((size_t)(b * Pp) + snn[k]) * Cc + c4 * 4);
        int c = c4 * 4;
        hT[(c + 0) * HT_STRIDE + k] = v4.x;
        hT[(c + 1) * HT_STRIDE + k] = v4.y;
        hT[(c + 2) * HT_STRIDE + k] = v4.z;
        hT[(c + 3) * HT_STRIDE + k] = v4.w;
    }
    for (int t2 = t; t2 < NB * 3; t2 += 256) {
        int k = t2 / 3, d = t2 - 3 * k;
        float cd = (d == 0) ? cx : ((d == 1) ? cy : cz);
        hT[(64 + d) * HT_STRIDE + k] =
            __fsub_rn(pos[((size_t)(b * Pp) + snn[k]) * 3 + d], cd);
    }
    // phase-lock both sub-units from here: shared weight streaming
    __syncthreads();

    const float R2A = (float)(0.2 * 0.2);
    const float R2B = (float)(0.4 * 0.4);
    const int tx = t & 31, ty = t >> 5;

    float* outrow = out + (size_t)bm * OUTC;
    // branch 2: K=64, 67->128->256, output channels [128,384)
    run_branch<64, 128, 256>(hT, h1T, sd2s, w2_0, b2_0, w2_1, b2_1,
                             outrow + 128, R2B, tx, ty, t);
    // branch 1: K=32 (prefix of sorted 64-NN), 67->64->128, channels [0,128)
    run_branch<32, 64, 128>(hT, h1T, sd2s, w1_0, b1_0, w1_1, b1_1,
                            outrow, R2A, tx, ty, t);
}

// ---------------------------------------------------------------------------
// launch
// ---------------------------------------------------------------------------
extern "C" void kernel_launch(void* const* d_in, const int* in_sizes, int n_in,
                              void* d_out, int out_size)
{
    const float* x    = (const float*)d_in[0];
    const float* pos  = (const float*)d_in[1];
    const float* w1_0 = (const float*)d_in[2];
    const float* b1_0 = (const float*)d_in[3];
    const float* w1_1 = (const float*)d_in[4];
    const float* b1_1 = (const float*)d_in[5];
    const float* w2_0 = (const float*)d_in[6];
    const float* b2_0 = (const float*)d_in[7];
    const float* w2_1 = (const float*)d_in[8];
    const float* b2_1 = (const float*)d_in[9];

    float* out   = (float*)d_out;
    float* pos_s = out + (size_t)Bb * Mm * OUTC;   // [out | pos_s] layout

    // reset progress counters every invocation (graph replay safe)
    void* paddr = nullptr;
    cudaGetSymbolAddress(&paddr, g_progress);
    cudaMemsetAsync(paddr, 0, sizeof(unsigned) * Bb);

    const int smem = 2 * WGF * 4;   // 107520 bytes
    cudaFuncSetAttribute(fused_kernel, cudaFuncAttributeMaxDynamicSharedMemorySize, smem);

    fused_kernel<<<Bb + 2 * Mm, 512, smem>>>(x, pos,
                                             w1_0, b1_0, w1_1, b1_1,
                                             w2_0, b2_0, w2_1, b2_1,
                                             out, pos_s);
}